// round 9
// baseline (speedup 1.0000x reference)
#include <cuda_runtime.h>

// ---------------- problem constants ----------------
#define N_PTS 32768
#define TILE_I 4096                                   // i-extent per block
#define TILE_J 1024                                   // j-extent per block
#define T_TILES (N_PTS / TILE_I)                      // 8
#define NSQUARES (T_TILES * (T_TILES + 1) / 2)        // 36 tile-squares
#define JCHUNKS (TILE_I / TILE_J)                     // 4
#define NPAIR_BLOCKS (NSQUARES * JCHUNKS)             // 144 blocks, 1 per SM
#define THREADS 512
#define IB 8                                          // i-points per thread (512*8 = 4096)
#define NG (IB / 2)                                   // 4 packed i-groups per thread
#define SCALE 3.5f
#define SCALE2 12.25f

// ---------------- device scratch (no allocs allowed) ----------------
__device__ double g_part[NPAIR_BLOCKS];  // per-block pair sums
__device__ double g_e1[NPAIR_BLOCKS];    // per-block sum p*log(1+d2)
__device__ double g_e2[NPAIR_BLOCKS];    // per-block sum p
__device__ double g_e3[NPAIR_BLOCKS];    // per-block sum p*log(p)
__device__ int    g_done;                // completion counter (self-resetting)

typedef unsigned long long u64;

__device__ __forceinline__ float frcp(float x) {
    float r;
    asm("rcp.approx.ftz.f32 %0, %1;" : "=f"(r) : "f"(x));
    return r;
}
__device__ __forceinline__ u64 pack2(float lo, float hi) {
    u64 r;
    asm("mov.b64 %0, {%1, %2};" : "=l"(r) : "f"(lo), "f"(hi));
    return r;
}
__device__ __forceinline__ void unpack2(u64 v, float& lo, float& hi) {
    asm("mov.b64 {%0, %1}, %2;" : "=f"(lo), "=f"(hi) : "l"(v));
}
__device__ __forceinline__ u64 fma2(u64 a, u64 b, u64 c) {
    u64 d;
    asm("fma.rn.f32x2 %0, %1, %2, %3;" : "=l"(d) : "l"(a), "l"(b), "l"(c));
    return d;
}
__device__ __forceinline__ u64 add2(u64 a, u64 b) {
    u64 d;
    asm("add.rn.f32x2 %0, %1, %2;" : "=l"(d) : "l"(a), "l"(b));
    return d;
}
__device__ __forceinline__ u64 mul2(u64 a, u64 b) {
    u64 d;
    asm("mul.rn.f32x2 %0, %1, %2;" : "=l"(d) : "l"(a), "l"(b));
    return d;
}

// ---------------- single fused kernel ----------------------------------------
// 144 blocks = 1 per SM, single wave. Each block:
//   1) one 4096x1024 rectangle of pair terms (quarter of a tile-square;
//      diagonal squares counted once, off-diagonal doubled by symmetry).
//      IB=8 register i-tile => half the LDS per pair, 8 independent rcp chains.
//   2) a 1/144 slice of the positive-edge terms (load-balanced)
//   3) last block to finish assembles the final scalar (no extra launches)
__global__ void __launch_bounds__(THREADS) k_fused(
        const float2* __restrict__ emb,
        const float* __restrict__ p,
        const int* __restrict__ heads,
        const int* __restrict__ tails,
        int E, int n, float* __restrict__ out) {
    __shared__ __align__(16) u64 sx[TILE_J];
    __shared__ __align__(16) u64 sy[TILE_J];
    __shared__ __align__(16) u64 sz[TILE_J];

    int q = blockIdx.x;

    // ================= phase 1: pair rectangle =================
    {
        int t = q >> 2;          // square id (0..35)
        int chunk = q & 3;       // j-chunk within the square
        // invert lower-triangular linear index: t = r*(r+1)/2 + c, c <= r
        int r = (int)((sqrtf(8.0f * (float)t + 1.0f) - 1.0f) * 0.5f);
        while ((r + 1) * (r + 2) / 2 <= t) r++;
        while (r * (r + 1) / 2 > t) r--;
        int c = t - r * (r + 1) / 2;
        int bi = c, bj = r;  // bi <= bj

        int jbase = bj * TILE_I + chunk * TILE_J;
        int ibase = bi * TILE_I;

        // cooperative j-tile load: scale + precompute, pre-broadcast packed
        for (int k = threadIdx.x; k < TILE_J; k += THREADS) {
            float2 e = emb[jbase + k];
            float x = e.x * SCALE;
            float y = e.y * SCALE;
            float sq = fmaf(x, x, y * y);
            sx[k] = pack2(x, x);
            sy[k] = pack2(y, y);
            sz[k] = pack2(1.0f + sq, 1.0f + sq);
        }
        __syncthreads();

        // per-thread i-points: IB=8 consecutive, packed 2 i's per register
        u64 m2[NG], n2[NG], s2[NG], acc2[NG];
        int i0 = ibase + threadIdx.x * IB;
#pragma unroll
        for (int g = 0; g < NG; g++) {
            float2 ea = emb[i0 + 2 * g];
            float2 eb = emb[i0 + 2 * g + 1];
            float xa = ea.x * SCALE, ya = ea.y * SCALE;
            float xb = eb.x * SCALE, yb = eb.y * SCALE;
            m2[g] = pack2(-2.0f * xa, -2.0f * xb);
            n2[g] = pack2(-2.0f * ya, -2.0f * yb);
            s2[g] = pack2(fmaf(xa, xa, ya * ya), fmaf(xb, xb, yb * yb));
            acc2[g] = pack2(0.0f, 0.0f);
        }

#pragma unroll 2
        for (int j = 0; j < TILE_J; j += 2) {
            ulonglong2 JX = *reinterpret_cast<const ulonglong2*>(&sx[j]);
            ulonglong2 JY = *reinterpret_cast<const ulonglong2*>(&sy[j]);
            ulonglong2 JZ = *reinterpret_cast<const ulonglong2*>(&sz[j]);
#pragma unroll
            for (int g = 0; g < NG; g++) {
                // denominators (1+d2) for (i_2g, i_2g+1) x (j, j+1)
                u64 d1 = fma2(m2[g], JX.x, fma2(n2[g], JY.x, add2(JZ.x, s2[g])));
                u64 d2 = fma2(m2[g], JX.y, fma2(n2[g], JY.y, add2(JZ.y, s2[g])));
                // 1/a + 1/b = (a+b) * rcp(a*b), packed per i-lane across j-pair
                u64 pr = mul2(d1, d2);
                u64 sm = add2(d1, d2);
                float plo, phi;
                unpack2(pr, plo, phi);
                u64 r2 = pack2(frcp(plo), frcp(phi));
                acc2[g] = fma2(sm, r2, acc2[g]);
            }
        }

        double dsum = 0.0;
#pragma unroll
        for (int g = 0; g < NG; g++) {
            float lo, hi;
            unpack2(acc2[g], lo, hi);
            dsum += (double)lo + (double)hi;
        }
        if (bi != bj) dsum *= 2.0;  // symmetry doubling

#pragma unroll
        for (int o = 16; o > 0; o >>= 1)
            dsum += __shfl_down_sync(0xffffffffu, dsum, o);

        double* sred = reinterpret_cast<double*>(sx);
        __syncthreads();
        if ((threadIdx.x & 31) == 0)
            sred[threadIdx.x >> 5] = dsum;
        __syncthreads();
        if (threadIdx.x == 0) {
            double v = 0.0;
#pragma unroll
            for (int w = 0; w < THREADS / 32; w++) v += sred[w];
            g_part[q] = v;
        }
    }

    // ================= phase 2: edge slice (1/144 of E) =================
    {
        int tid = q * THREADS + threadIdx.x;
        int stride = NPAIR_BLOCKS * THREADS;
        float s1 = 0.0f, sp = 0.0f, se = 0.0f;
        for (int e = tid; e < E; e += stride) {
            int h = heads[e], tl = tails[e];
            float2 A = emb[h];
            float2 B = emb[tl];
            float dx = A.x - B.x;
            float dy = A.y - B.y;
            float d2 = SCALE2 * fmaf(dx, dx, dy * dy);
            float pe = p[e];
            s1 = fmaf(pe, __logf(1.0f + d2), s1);  // p * log(1+d2)
            sp += pe;
            se = fmaf(pe, __logf(pe), se);          // p * log(p)
        }
        double d1 = (double)s1, d2s = (double)sp, d3 = (double)se;
#pragma unroll
        for (int o = 16; o > 0; o >>= 1) {
            d1  += __shfl_down_sync(0xffffffffu, d1, o);
            d2s += __shfl_down_sync(0xffffffffu, d2s, o);
            d3  += __shfl_down_sync(0xffffffffu, d3, o);
        }
        double* sh1 = reinterpret_cast<double*>(sy);
        double* sh2 = sh1 + (THREADS / 32);
        double* sh3 = sh2 + (THREADS / 32);
        __syncthreads();
        if ((threadIdx.x & 31) == 0) {
            int w = threadIdx.x >> 5;
            sh1[w] = d1; sh2[w] = d2s; sh3[w] = d3;
        }
        __syncthreads();
        if (threadIdx.x == 0) {
            double v1 = 0.0, v2 = 0.0, v3 = 0.0;
#pragma unroll
            for (int w = 0; w < THREADS / 32; w++) {
                v1 += sh1[w]; v2 += sh2[w]; v3 += sh3[w];
            }
            g_e1[q] = v1; g_e2[q] = v2; g_e3[q] = v3;
        }
    }

    // ================= phase 3: last block assembles the scalar =================
    int lastflag = 0;
    if (threadIdx.x == 0) {
        __threadfence();  // make this block's partials visible
        lastflag = (atomicAdd(&g_done, 1) == NPAIR_BLOCKS - 1) ? 1 : 0;
    }
    if (threadIdx.x < 32) {
        lastflag = __shfl_sync(0xffffffffu, lastflag, 0);
        if (lastflag) {
            __threadfence();  // acquire all other blocks' partials
            double z = 0.0, e1 = 0.0, e2 = 0.0, e3 = 0.0;
            for (int i = threadIdx.x; i < NPAIR_BLOCKS; i += 32) {
                z  += g_part[i];
                e1 += g_e1[i];
                e2 += g_e2[i];
                e3 += g_e3[i];
            }
#pragma unroll
            for (int o = 16; o > 0; o >>= 1) {
                z  += __shfl_down_sync(0xffffffffu, z, o);
                e1 += __shfl_down_sync(0xffffffffu, e1, o);
                e2 += __shfl_down_sync(0xffffffffu, e2, o);
                e3 += __shfl_down_sync(0xffffffffu, e3, o);
            }
            if (threadIdx.x == 0) {
                double Z = z - (double)n;  // remove diagonal (each term = 1)
                out[0] = (float)(e1 + log(Z) * e2 + e3);
                g_done = 0;  // self-reset for graph replay determinism
            }
        }
    }
}

// ---------------- launch ------------------------------------------------------
extern "C" void kernel_launch(void* const* d_in, const int* in_sizes, int n_in,
                              void* d_out, int out_size) {
    const float2* emb   = (const float2*)d_in[0];
    const float*  p     = (const float*)d_in[1];
    const int*    heads = (const int*)d_in[2];
    const int*    tails = (const int*)d_in[3];
    int n = in_sizes[0] / 2;
    int E = in_sizes[1];

    k_fused<<<NPAIR_BLOCKS, THREADS>>>(emb, p, heads, tails, E, n, (float*)d_out);
}

// round 10
// speedup vs baseline: 1.0592x; 1.0592x over previous
#include <cuda_runtime.h>

// ---------------- problem constants ----------------
#define N_PTS 32768
#define TILE_I 4096                                   // i-extent per block
#define TILE_J 1024                                   // j-extent per block
#define T_TILES (N_PTS / TILE_I)                      // 8
#define NSQUARES (T_TILES * (T_TILES + 1) / 2)        // 36 tile-squares
#define JCHUNKS (TILE_I / TILE_J)                     // 4
#define NPAIR_BLOCKS (NSQUARES * JCHUNKS)             // 144 blocks, 1 per SM
#define THREADS 1024                                  // 8 warps per SMSP
#define IB 4                                          // i-points per thread (1024*4 = 4096)
#define NG (IB / 2)                                   // 2 packed i-groups per thread
#define SCALE 3.5f
#define SCALE2 12.25f

// ---------------- device scratch (no allocs allowed) ----------------
__device__ double g_part[NPAIR_BLOCKS];  // per-block pair sums
__device__ double g_e1[NPAIR_BLOCKS];    // per-block sum p*log(1+d2)
__device__ double g_e2[NPAIR_BLOCKS];    // per-block sum p
__device__ double g_e3[NPAIR_BLOCKS];    // per-block sum p*log(p)
__device__ int    g_done;                // completion counter (self-resetting)

typedef unsigned long long u64;

__device__ __forceinline__ float frcp(float x) {
    float r;
    asm("rcp.approx.ftz.f32 %0, %1;" : "=f"(r) : "f"(x));
    return r;
}
__device__ __forceinline__ u64 pack2(float lo, float hi) {
    u64 r;
    asm("mov.b64 %0, {%1, %2};" : "=l"(r) : "f"(lo), "f"(hi));
    return r;
}
__device__ __forceinline__ void unpack2(u64 v, float& lo, float& hi) {
    asm("mov.b64 {%0, %1}, %2;" : "=f"(lo), "=f"(hi) : "l"(v));
}
__device__ __forceinline__ u64 fma2(u64 a, u64 b, u64 c) {
    u64 d;
    asm("fma.rn.f32x2 %0, %1, %2, %3;" : "=l"(d) : "l"(a), "l"(b), "l"(c));
    return d;
}
__device__ __forceinline__ u64 add2(u64 a, u64 b) {
    u64 d;
    asm("add.rn.f32x2 %0, %1, %2;" : "=l"(d) : "l"(a), "l"(b));
    return d;
}
__device__ __forceinline__ u64 mul2(u64 a, u64 b) {
    u64 d;
    asm("mul.rn.f32x2 %0, %1, %2;" : "=l"(d) : "l"(a), "l"(b));
    return d;
}

// ---------------- single fused kernel ----------------------------------------
// 144 blocks x 1024 threads = 1 block/SM, 8 warps/SMSP (2x the latency cover
// of previous rounds; per-warp instruction stream unchanged). Each block:
//   1) one 4096x1024 rectangle of pair terms (diagonal squares counted once,
//      off-diagonal doubled by symmetry)
//   2) a 1/144 slice of the positive-edge terms
//   3) last block to finish assembles the final scalar
__global__ void __launch_bounds__(THREADS) k_fused(
        const float2* __restrict__ emb,
        const float* __restrict__ p,
        const int* __restrict__ heads,
        const int* __restrict__ tails,
        int E, int n, float* __restrict__ out) {
    __shared__ __align__(16) u64 sx[TILE_J];
    __shared__ __align__(16) u64 sy[TILE_J];
    __shared__ __align__(16) u64 sz[TILE_J];

    int q = blockIdx.x;

    // ================= phase 1: pair rectangle =================
    {
        int t = q >> 2;          // square id (0..35)
        int chunk = q & 3;       // j-chunk within the square
        // invert lower-triangular linear index: t = r*(r+1)/2 + c, c <= r
        int r = (int)((sqrtf(8.0f * (float)t + 1.0f) - 1.0f) * 0.5f);
        while ((r + 1) * (r + 2) / 2 <= t) r++;
        while (r * (r + 1) / 2 > t) r--;
        int c = t - r * (r + 1) / 2;
        int bi = c, bj = r;  // bi <= bj

        int jbase = bj * TILE_I + chunk * TILE_J;
        int ibase = bi * TILE_I;

        // cooperative j-tile load: scale + precompute, pre-broadcast packed
        for (int k = threadIdx.x; k < TILE_J; k += THREADS) {
            float2 e = emb[jbase + k];
            float x = e.x * SCALE;
            float y = e.y * SCALE;
            float sq = fmaf(x, x, y * y);
            sx[k] = pack2(x, x);
            sy[k] = pack2(y, y);
            sz[k] = pack2(1.0f + sq, 1.0f + sq);
        }
        __syncthreads();

        // per-thread i-points: IB=4 consecutive, packed 2 i's per register
        u64 m2[NG], n2[NG], s2[NG], acc2[NG];
        int i0 = ibase + threadIdx.x * IB;
#pragma unroll
        for (int g = 0; g < NG; g++) {
            float2 ea = emb[i0 + 2 * g];
            float2 eb = emb[i0 + 2 * g + 1];
            float xa = ea.x * SCALE, ya = ea.y * SCALE;
            float xb = eb.x * SCALE, yb = eb.y * SCALE;
            m2[g] = pack2(-2.0f * xa, -2.0f * xb);
            n2[g] = pack2(-2.0f * ya, -2.0f * yb);
            s2[g] = pack2(fmaf(xa, xa, ya * ya), fmaf(xb, xb, yb * yb));
            acc2[g] = pack2(0.0f, 0.0f);
        }

#pragma unroll 4
        for (int j = 0; j < TILE_J; j += 2) {
            ulonglong2 JX = *reinterpret_cast<const ulonglong2*>(&sx[j]);
            ulonglong2 JY = *reinterpret_cast<const ulonglong2*>(&sy[j]);
            ulonglong2 JZ = *reinterpret_cast<const ulonglong2*>(&sz[j]);
#pragma unroll
            for (int g = 0; g < NG; g++) {
                // denominators (1+d2) for (i_2g, i_2g+1) x (j, j+1)
                u64 d1 = fma2(m2[g], JX.x, fma2(n2[g], JY.x, add2(JZ.x, s2[g])));
                u64 d2 = fma2(m2[g], JX.y, fma2(n2[g], JY.y, add2(JZ.y, s2[g])));
                // 1/a + 1/b = (a+b) * rcp(a*b), packed per i-lane across j-pair
                u64 pr = mul2(d1, d2);
                u64 sm = add2(d1, d2);
                float plo, phi;
                unpack2(pr, plo, phi);
                u64 r2 = pack2(frcp(plo), frcp(phi));
                acc2[g] = fma2(sm, r2, acc2[g]);
            }
        }

        double dsum = 0.0;
#pragma unroll
        for (int g = 0; g < NG; g++) {
            float lo, hi;
            unpack2(acc2[g], lo, hi);
            dsum += (double)lo + (double)hi;
        }
        if (bi != bj) dsum *= 2.0;  // symmetry doubling

#pragma unroll
        for (int o = 16; o > 0; o >>= 1)
            dsum += __shfl_down_sync(0xffffffffu, dsum, o);

        double* sred = reinterpret_cast<double*>(sx);
        __syncthreads();
        if ((threadIdx.x & 31) == 0)
            sred[threadIdx.x >> 5] = dsum;
        __syncthreads();
        if (threadIdx.x == 0) {
            double v = 0.0;
#pragma unroll
            for (int w = 0; w < THREADS / 32; w++) v += sred[w];
            g_part[q] = v;
        }
    }

    // ================= phase 2: edge slice (1/144 of E) =================
    {
        int tid = q * THREADS + threadIdx.x;
        int stride = NPAIR_BLOCKS * THREADS;
        float s1 = 0.0f, sp = 0.0f, se = 0.0f;
        for (int e = tid; e < E; e += stride) {
            int h = heads[e], tl = tails[e];
            float2 A = emb[h];
            float2 B = emb[tl];
            float dx = A.x - B.x;
            float dy = A.y - B.y;
            float d2 = SCALE2 * fmaf(dx, dx, dy * dy);
            float pe = p[e];
            s1 = fmaf(pe, __logf(1.0f + d2), s1);  // p * log(1+d2)
            sp += pe;
            se = fmaf(pe, __logf(pe), se);          // p * log(p)
        }
        double d1 = (double)s1, d2s = (double)sp, d3 = (double)se;
#pragma unroll
        for (int o = 16; o > 0; o >>= 1) {
            d1  += __shfl_down_sync(0xffffffffu, d1, o);
            d2s += __shfl_down_sync(0xffffffffu, d2s, o);
            d3  += __shfl_down_sync(0xffffffffu, d3, o);
        }
        double* sh1 = reinterpret_cast<double*>(sy);
        double* sh2 = sh1 + (THREADS / 32);
        double* sh3 = sh2 + (THREADS / 32);
        __syncthreads();
        if ((threadIdx.x & 31) == 0) {
            int w = threadIdx.x >> 5;
            sh1[w] = d1; sh2[w] = d2s; sh3[w] = d3;
        }
        __syncthreads();
        if (threadIdx.x == 0) {
            double v1 = 0.0, v2 = 0.0, v3 = 0.0;
#pragma unroll
            for (int w = 0; w < THREADS / 32; w++) {
                v1 += sh1[w]; v2 += sh2[w]; v3 += sh3[w];
            }
            g_e1[q] = v1; g_e2[q] = v2; g_e3[q] = v3;
        }
    }

    // ================= phase 3: last block assembles the scalar =================
    int lastflag = 0;
    if (threadIdx.x == 0) {
        __threadfence();  // make this block's partials visible
        lastflag = (atomicAdd(&g_done, 1) == NPAIR_BLOCKS - 1) ? 1 : 0;
    }
    if (threadIdx.x < 32) {
        lastflag = __shfl_sync(0xffffffffu, lastflag, 0);
        if (lastflag) {
            __threadfence();  // acquire all other blocks' partials
            double z = 0.0, e1 = 0.0, e2 = 0.0, e3 = 0.0;
            for (int i = threadIdx.x; i < NPAIR_BLOCKS; i += 32) {
                z  += g_part[i];
                e1 += g_e1[i];
                e2 += g_e2[i];
                e3 += g_e3[i];
            }
#pragma unroll
            for (int o = 16; o > 0; o >>= 1) {
                z  += __shfl_down_sync(0xffffffffu, z, o);
                e1 += __shfl_down_sync(0xffffffffu, e1, o);
                e2 += __shfl_down_sync(0xffffffffu, e2, o);
                e3 += __shfl_down_sync(0xffffffffu, e3, o);
            }
            if (threadIdx.x == 0) {
                double Z = z - (double)n;  // remove diagonal (each term = 1)
                out[0] = (float)(e1 + log(Z) * e2 + e3);
                g_done = 0;  // self-reset for graph replay determinism
            }
        }
    }
}

// ---------------- launch ------------------------------------------------------
extern "C" void kernel_launch(void* const* d_in, const int* in_sizes, int n_in,
                              void* d_out, int out_size) {
    const float2* emb   = (const float2*)d_in[0];
    const float*  p     = (const float*)d_in[1];
    const int*    heads = (const int*)d_in[2];
    const int*    tails = (const int*)d_in[3];
    int n = in_sizes[0] / 2;
    int E = in_sizes[1];

    k_fused<<<NPAIR_BLOCKS, THREADS>>>(emb, p, heads, tails, E, n, (float*)d_out);
}